// round 1
// baseline (speedup 1.0000x reference)
#include <cuda_runtime.h>

// ----------------------------------------------------------------------------
// EdgeBiasedAttention: B=32, N=512, D=256, H=8, HD=32
//   q,k,v = h @ W^T ; scores = qk^T/sqrt(32) + W_e[h]*edge ; mask ; softmax ;
//   out = (attn @ v) reshaped ; out @ W_o^T
// Round 1: fp32 CUDA-core baseline. Projections via 128x128x16 register-blocked
// GEMM; attention via flash-style online softmax (1 thread = 1 query row).
// ----------------------------------------------------------------------------

#define BATCH 32
#define NSEQ  512
#define DMODEL 256
#define NHEAD 8
#define HDIM  32
#define MROWS (BATCH * NSEQ)  // 16384

// scratch (device globals: allocation-free)
__device__ float g_q [MROWS * DMODEL];
__device__ float g_k [MROWS * DMODEL];
__device__ float g_v [MROWS * DMODEL];
__device__ float g_ao[MROWS * DMODEL];

// ----------------------------------------------------------------------------
// Projection GEMM: C[M,256] = X[M,256] @ W[256,256]^T   (W stored [out,in])
// Block tile 128x128, K-panel 16, 256 threads, 8x8 per thread.
// ----------------------------------------------------------------------------
__global__ __launch_bounds__(256) void proj_gemm(const float* __restrict__ X,
                                                 const float* __restrict__ W,
                                                 float* __restrict__ C)
{
    __shared__ float Xs[16][132];
    __shared__ float Ws[16][132];

    const int t  = threadIdx.x;
    const int m0 = blockIdx.y * 128;
    const int n0 = blockIdx.x * 128;
    const int tx = t & 15;
    const int ty = t >> 4;

    float acc[8][8];
#pragma unroll
    for (int r = 0; r < 8; ++r)
#pragma unroll
        for (int c = 0; c < 8; ++c) acc[r][c] = 0.f;

    for (int k0 = 0; k0 < DMODEL; k0 += 16) {
        // fill tiles (transposed to [k][m] / [k][n]), float4 global loads
#pragma unroll
        for (int i = 0; i < 2; ++i) {
            int idx = t + i * 256;          // 0..511
            int row = idx >> 2;             // 0..127
            int q   = (idx & 3) << 2;       // 0,4,8,12
            float4 xv = *(const float4*)(X + (size_t)(m0 + row) * DMODEL + k0 + q);
            Xs[q + 0][row] = xv.x; Xs[q + 1][row] = xv.y;
            Xs[q + 2][row] = xv.z; Xs[q + 3][row] = xv.w;
            float4 wv = *(const float4*)(W + (size_t)(n0 + row) * DMODEL + k0 + q);
            Ws[q + 0][row] = wv.x; Ws[q + 1][row] = wv.y;
            Ws[q + 2][row] = wv.z; Ws[q + 3][row] = wv.w;
        }
        __syncthreads();

#pragma unroll
        for (int kk = 0; kk < 16; ++kk) {
            float4 A0 = *(const float4*)&Xs[kk][ty * 8];
            float4 A1 = *(const float4*)&Xs[kk][ty * 8 + 4];
            float4 B0 = *(const float4*)&Ws[kk][tx * 8];
            float4 B1 = *(const float4*)&Ws[kk][tx * 8 + 4];
            float a[8]  = {A0.x, A0.y, A0.z, A0.w, A1.x, A1.y, A1.z, A1.w};
            float bb[8] = {B0.x, B0.y, B0.z, B0.w, B1.x, B1.y, B1.z, B1.w};
#pragma unroll
            for (int r = 0; r < 8; ++r)
#pragma unroll
                for (int c = 0; c < 8; ++c)
                    acc[r][c] += a[r] * bb[c];
        }
        __syncthreads();
    }

#pragma unroll
    for (int r = 0; r < 8; ++r) {
        float* dst = C + (size_t)(m0 + ty * 8 + r) * DMODEL + n0 + tx * 8;
        *(float4*)(dst)     = make_float4(acc[r][0], acc[r][1], acc[r][2], acc[r][3]);
        *(float4*)(dst + 4) = make_float4(acc[r][4], acc[r][5], acc[r][6], acc[r][7]);
    }
}

// ----------------------------------------------------------------------------
// Attention: per block = (64 query rows) x (one b,h pair). 64 threads,
// 1 thread per query, stream K/V/edge/mask in tiles of 64 keys.
// ----------------------------------------------------------------------------
__device__ __forceinline__ float dot4f(float4 a, float4 b) {
    return a.x * b.x + a.y * b.y + a.z * b.z + a.w * b.w;
}
__device__ __forceinline__ void mul4f(float4& a, float c) {
    a.x *= c; a.y *= c; a.z *= c; a.w *= c;
}
__device__ __forceinline__ void fma4f(float4& a, float p, float4 v) {
    a.x += p * v.x; a.y += p * v.y; a.z += p * v.z; a.w += p * v.w;
}

__global__ __launch_bounds__(64) void attn_kernel(
    const float* __restrict__ Q, const float* __restrict__ K,
    const float* __restrict__ V, const float* __restrict__ edge,
    const int*   __restrict__ mask, const float* __restrict__ We,
    float* __restrict__ AO)
{
    __shared__ float4 Ks[64][8];
    __shared__ float4 Vs[64][8];
    __shared__ float  bs[64][65];   // edge bias (masked -> -3e38); pad -> conflict-free reads

    const int t     = threadIdx.x;          // 0..63
    const int bh    = blockIdx.y;            // 0..255
    const int b     = bh >> 3;
    const int hh    = bh & 7;
    const int qbase = blockIdx.x << 6;       // 0,64,...,448
    const int qi    = qbase + t;
    const float we  = We[hh];
    const float scale = 0.17677669529663687f; // 1/sqrt(32)

    // q row -> registers
    const float4* qp = (const float4*)(Q + ((size_t)b * NSEQ + qi) * DMODEL + hh * HDIM);
    float4 q[8];
#pragma unroll
    for (int i = 0; i < 8; ++i) q[i] = qp[i];

    float m = -1e30f, l = 0.f;
    float4 a[8];
#pragma unroll
    for (int i = 0; i < 8; ++i) a[i] = make_float4(0.f, 0.f, 0.f, 0.f);

    for (int jt = 0; jt < NSEQ; jt += 64) {
        const float4* kb = (const float4*)(K + ((size_t)b * NSEQ + jt) * DMODEL + hh * HDIM);
        const float4* vb = (const float4*)(V + ((size_t)b * NSEQ + jt) * DMODEL + hh * HDIM);
#pragma unroll
        for (int i = 0; i < 8; ++i) {
            int idx = t + i * 64;           // 0..511
            int row = idx >> 3, c = idx & 7;
            Ks[row][c] = kb[(size_t)row * 64 + c];   // row stride = 256 floats
            Vs[row][c] = vb[(size_t)row * 64 + c];
        }
        const float4* e4 = (const float4*)(edge + ((size_t)b * NSEQ + qbase) * NSEQ + jt);
        const int4*   m4 = (const int4*)  ((const char*)mask + (((size_t)b * NSEQ + qbase) * NSEQ + jt) * 4);
#pragma unroll
        for (int i = 0; i < 16; ++i) {
            int idx = t + i * 64;           // 0..1023
            int row = idx >> 4, c4 = idx & 15;
            float4 ev = e4[(size_t)row * 128 + c4];  // row stride = 512 floats
            int4   mv = m4[(size_t)row * 128 + c4];
            float* dst = &bs[row][c4 * 4];
            dst[0] = mv.x ? we * ev.x : -3e38f;
            dst[1] = mv.y ? we * ev.y : -3e38f;
            dst[2] = mv.z ? we * ev.z : -3e38f;
            dst[3] = mv.w ? we * ev.w : -3e38f;
        }
        __syncthreads();

#pragma unroll 2
        for (int j = 0; j < 64; ++j) {
            float s0 = dot4f(q[0], Ks[j][0]) + dot4f(q[1], Ks[j][1]);
            float s1 = dot4f(q[2], Ks[j][2]) + dot4f(q[3], Ks[j][3]);
            float s2 = dot4f(q[4], Ks[j][4]) + dot4f(q[5], Ks[j][5]);
            float s3 = dot4f(q[6], Ks[j][6]) + dot4f(q[7], Ks[j][7]);
            float s  = ((s0 + s1) + (s2 + s3)) * scale + bs[t][j];

            if (s > m) {
                float corr = __expf(m - s);
                m = s;
                l *= corr;
#pragma unroll
                for (int i = 0; i < 8; ++i) mul4f(a[i], corr);
            }
            float p = __expf(s - m);
            l += p;
#pragma unroll
            for (int i = 0; i < 8; ++i) fma4f(a[i], p, Vs[j][i]);
        }
        __syncthreads();
    }

    const float inv = 1.0f / l;
    float4* op = (float4*)(AO + ((size_t)b * NSEQ + qi) * DMODEL + hh * HDIM);
#pragma unroll
    for (int i = 0; i < 8; ++i)
        op[i] = make_float4(a[i].x * inv, a[i].y * inv, a[i].z * inv, a[i].w * inv);
}

// ----------------------------------------------------------------------------
// launch
// ----------------------------------------------------------------------------
extern "C" void kernel_launch(void* const* d_in, const int* in_sizes, int n_in,
                              void* d_out, int out_size)
{
    const float* h    = (const float*)d_in[0];
    const float* edge = (const float*)d_in[1];
    const int*   mask = (const int*)  d_in[2];  // nonzero test works for int32 & fp32 encodings
    const float* Wq   = (const float*)d_in[3];
    const float* Wk   = (const float*)d_in[4];
    const float* Wv   = (const float*)d_in[5];
    const float* We   = (const float*)d_in[6];
    const float* Wo   = (const float*)d_in[7];
    float* out = (float*)d_out;

    float *qs, *ks, *vs, *ao;
    cudaGetSymbolAddress((void**)&qs, g_q);
    cudaGetSymbolAddress((void**)&ks, g_k);
    cudaGetSymbolAddress((void**)&vs, g_v);
    cudaGetSymbolAddress((void**)&ao, g_ao);

    dim3 pgrid(DMODEL / 128, MROWS / 128);   // (2, 128)
    proj_gemm<<<pgrid, 256>>>(h, Wq, qs);
    proj_gemm<<<pgrid, 256>>>(h, Wk, ks);
    proj_gemm<<<pgrid, 256>>>(h, Wv, vs);

    attn_kernel<<<dim3(NSEQ / 64, BATCH * NHEAD), 64>>>(qs, ks, vs, edge, mask, We, ao);

    proj_gemm<<<pgrid, 256>>>(ao, Wo, out);
}

// round 2
// speedup vs baseline: 3.0513x; 3.0513x over previous
#include <cuda_runtime.h>
#include <math.h>

// ----------------------------------------------------------------------------
// EdgeBiasedAttention — TF32 tensor-core version (mma.sync m16n8k8)
// B=32, N=512, D=256, H=8, HD=32
// ----------------------------------------------------------------------------

#define BATCH 32
#define NSEQ  512
#define DMODEL 256
#define NHEAD 8
#define HDIM  32
#define MROWS (BATCH * NSEQ)  // 16384

__device__ float g_q [MROWS * DMODEL];
__device__ float g_k [MROWS * DMODEL];
__device__ float g_v [MROWS * DMODEL];
__device__ float g_ao[MROWS * DMODEL];

__device__ __forceinline__ unsigned f2tf(float x) {
    unsigned r;
    asm("cvt.rna.tf32.f32 %0, %1;" : "=r"(r) : "f"(x));
    return r;
}

__device__ __forceinline__ void mma_tf32(float c[4],
                                         unsigned a0, unsigned a1, unsigned a2, unsigned a3,
                                         unsigned b0, unsigned b1)
{
    asm volatile(
        "mma.sync.aligned.m16n8k8.row.col.f32.tf32.tf32.f32 "
        "{%0,%1,%2,%3}, {%4,%5,%6,%7}, {%8,%9}, {%0,%1,%2,%3};"
        : "+f"(c[0]), "+f"(c[1]), "+f"(c[2]), "+f"(c[3])
        : "r"(a0), "r"(a1), "r"(a2), "r"(a3), "r"(b0), "r"(b1));
}

// ----------------------------------------------------------------------------
// TF32 GEMM: C[M,256] = X[M,256] @ W[256,256]^T   (W stored [out,in])
// Block 128x128, BK=32, 256 threads (8 warps), warp tile 64x32.
// ----------------------------------------------------------------------------
#define GLDK 36   // 32 + pad4

__global__ __launch_bounds__(256) void gemm_tf32(const float* __restrict__ X,
                                                 const float* __restrict__ W,
                                                 float* __restrict__ C)
{
    __shared__ unsigned Xs[128 * GLDK];
    __shared__ unsigned Ws[128 * GLDK];

    const int t    = threadIdx.x;
    const int warp = t >> 5, lane = t & 31;
    const int g    = lane >> 2, l = lane & 3;
    const int m0   = blockIdx.y * 128;
    const int n0   = blockIdx.x * 128;
    const int wm   = (warp >> 2) * 64;   // 0 or 64
    const int wn   = (warp & 3) * 32;    // 0,32,64,96

    float acc[4][4][4];
#pragma unroll
    for (int mt = 0; mt < 4; ++mt)
#pragma unroll
        for (int nt = 0; nt < 4; ++nt)
#pragma unroll
            for (int i = 0; i < 4; ++i) acc[mt][nt][i] = 0.f;

    for (int k0 = 0; k0 < DMODEL; k0 += 32) {
#pragma unroll
        for (int i = 0; i < 4; ++i) {
            int idx = t + i * 256;          // 0..1023
            int row = idx >> 3, c4 = idx & 7;
            float4 xv = *(const float4*)(X + (size_t)(m0 + row) * DMODEL + k0 + c4 * 4);
            unsigned* xd = &Xs[row * GLDK + c4 * 4];
            xd[0] = f2tf(xv.x); xd[1] = f2tf(xv.y); xd[2] = f2tf(xv.z); xd[3] = f2tf(xv.w);
            float4 wv = *(const float4*)(W + (size_t)(n0 + row) * DMODEL + k0 + c4 * 4);
            unsigned* wd = &Ws[row * GLDK + c4 * 4];
            wd[0] = f2tf(wv.x); wd[1] = f2tf(wv.y); wd[2] = f2tf(wv.z); wd[3] = f2tf(wv.w);
        }
        __syncthreads();

#pragma unroll
        for (int ks = 0; ks < 4; ++ks) {
            const int k = ks * 8;
            unsigned a[4][4];
#pragma unroll
            for (int mt = 0; mt < 4; ++mt) {
                int r = wm + mt * 16;
                a[mt][0] = Xs[(r + g) * GLDK + k + l];
                a[mt][1] = Xs[(r + g + 8) * GLDK + k + l];
                a[mt][2] = Xs[(r + g) * GLDK + k + l + 4];
                a[mt][3] = Xs[(r + g + 8) * GLDK + k + l + 4];
            }
            unsigned b[4][2];
#pragma unroll
            for (int nt = 0; nt < 4; ++nt) {
                int cn = wn + nt * 8;
                b[nt][0] = Ws[(cn + g) * GLDK + k + l];
                b[nt][1] = Ws[(cn + g) * GLDK + k + l + 4];
            }
#pragma unroll
            for (int mt = 0; mt < 4; ++mt)
#pragma unroll
                for (int nt = 0; nt < 4; ++nt)
                    mma_tf32(acc[mt][nt], a[mt][0], a[mt][1], a[mt][2], a[mt][3],
                             b[nt][0], b[nt][1]);
        }
        __syncthreads();
    }

#pragma unroll
    for (int mt = 0; mt < 4; ++mt) {
#pragma unroll
        for (int nt = 0; nt < 4; ++nt) {
            int r = m0 + wm + mt * 16 + g;
            int c = n0 + wn + nt * 8 + 2 * l;
            *(float2*)(C + (size_t)r * DMODEL + c)       = make_float2(acc[mt][nt][0], acc[mt][nt][1]);
            *(float2*)(C + (size_t)(r + 8) * DMODEL + c) = make_float2(acc[mt][nt][2], acc[mt][nt][3]);
        }
    }
}

// ----------------------------------------------------------------------------
// Attention (TF32 mma): block = 64 queries x one (b,h), 128 threads (4 warps),
// each warp owns 16 query rows. Streams 8 key tiles of 64.
// ----------------------------------------------------------------------------
#define ALD 36    // K/V/Q row stride (32+4)
#define PLD 68    // P/bias row stride (64+4)

__global__ __launch_bounds__(128) void attn_tf32(
    const float* __restrict__ Q, const float* __restrict__ K,
    const float* __restrict__ V, const float* __restrict__ edge,
    const int*   __restrict__ mask, const float* __restrict__ We,
    float* __restrict__ AO)
{
    __shared__ unsigned Qs[64 * ALD];
    __shared__ unsigned Ks[64 * ALD];
    __shared__ unsigned Vs[64 * ALD];
    __shared__ float    Ps[64 * PLD];   // bias, then P

    const int t    = threadIdx.x;
    const int warp = t >> 5, lane = t & 31;
    const int g    = lane >> 2, l = lane & 3;
    const int bh   = blockIdx.y;
    const int b    = bh >> 3, hh = bh & 7;
    const int q0   = blockIdx.x * 64;
    const int wq   = warp * 16;
    const float we = We[hh];
    const float scale = 0.17677669529663687f;   // 1/sqrt(32)

    // stage Q tile (64 x 32), tf32-converted
#pragma unroll
    for (int i = 0; i < 4; ++i) {
        int idx = t + i * 128;            // 0..511
        int row = idx >> 3, c4 = idx & 7;
        float4 qv = *(const float4*)(Q + ((size_t)(b * NSEQ + q0 + row)) * DMODEL + hh * HDIM + c4 * 4);
        unsigned* d = &Qs[row * ALD + c4 * 4];
        d[0] = f2tf(qv.x); d[1] = f2tf(qv.y); d[2] = f2tf(qv.z); d[3] = f2tf(qv.w);
    }

    float m0r = -1e30f, m1r = -1e30f, l0r = 0.f, l1r = 0.f;
    float o[4][4];
#pragma unroll
    for (int nt = 0; nt < 4; ++nt)
#pragma unroll
        for (int i = 0; i < 4; ++i) o[nt][i] = 0.f;

    for (int jt = 0; jt < NSEQ; jt += 64) {
        // stage K, V tiles (64 x 32)
#pragma unroll
        for (int i = 0; i < 4; ++i) {
            int idx = t + i * 128;
            int row = idx >> 3, c4 = idx & 7;
            size_t goff = ((size_t)(b * NSEQ + jt + row)) * DMODEL + hh * HDIM + c4 * 4;
            float4 kv = *(const float4*)(K + goff);
            unsigned* kd = &Ks[row * ALD + c4 * 4];
            kd[0] = f2tf(kv.x); kd[1] = f2tf(kv.y); kd[2] = f2tf(kv.z); kd[3] = f2tf(kv.w);
            float4 vv = *(const float4*)(V + goff);
            unsigned* vd = &Vs[row * ALD + c4 * 4];
            vd[0] = f2tf(vv.x); vd[1] = f2tf(vv.y); vd[2] = f2tf(vv.z); vd[3] = f2tf(vv.w);
        }
        // stage bias tile (64 x 64): we*edge, masked -> -1e30
#pragma unroll
        for (int i = 0; i < 8; ++i) {
            int idx = t + i * 128;         // 0..1023
            int row = idx >> 4, c4 = idx & 15;
            size_t goff = ((size_t)(b * NSEQ + q0 + row)) * NSEQ + jt + c4 * 4;
            float4 ev = *(const float4*)(edge + goff);
            int4   mv = *(const int4*)(mask + goff);
            float4 bv;
            bv.x = mv.x ? we * ev.x : -1e30f;
            bv.y = mv.y ? we * ev.y : -1e30f;
            bv.z = mv.z ? we * ev.z : -1e30f;
            bv.w = mv.w ? we * ev.w : -1e30f;
            *(float4*)&Ps[row * PLD + c4 * 4] = bv;
        }
        __syncthreads();

        // S = Q @ K^T : warp computes 16 x 64 in 8 n-tiles
        float s[8][4];
#pragma unroll
        for (int nt = 0; nt < 8; ++nt)
#pragma unroll
            for (int i = 0; i < 4; ++i) s[nt][i] = 0.f;

#pragma unroll
        for (int ks = 0; ks < 4; ++ks) {
            const int k = ks * 8;
            unsigned a0 = Qs[(wq + g) * ALD + k + l];
            unsigned a1 = Qs[(wq + g + 8) * ALD + k + l];
            unsigned a2 = Qs[(wq + g) * ALD + k + l + 4];
            unsigned a3 = Qs[(wq + g + 8) * ALD + k + l + 4];
#pragma unroll
            for (int nt = 0; nt < 8; ++nt) {
                unsigned b0 = Ks[(nt * 8 + g) * ALD + k + l];
                unsigned b1 = Ks[(nt * 8 + g) * ALD + k + l + 4];
                mma_tf32(s[nt], a0, a1, a2, a3, b0, b1);
            }
        }

        // epilogue: scale + bias, online softmax stats
        float mn0 = m0r, mn1 = m1r;
#pragma unroll
        for (int nt = 0; nt < 8; ++nt) {
            int c = nt * 8 + 2 * l;
            float2 b01 = *(float2*)&Ps[(wq + g) * PLD + c];
            float2 b23 = *(float2*)&Ps[(wq + g + 8) * PLD + c];
            s[nt][0] = s[nt][0] * scale + b01.x;
            s[nt][1] = s[nt][1] * scale + b01.y;
            s[nt][2] = s[nt][2] * scale + b23.x;
            s[nt][3] = s[nt][3] * scale + b23.y;
            mn0 = fmaxf(mn0, fmaxf(s[nt][0], s[nt][1]));
            mn1 = fmaxf(mn1, fmaxf(s[nt][2], s[nt][3]));
        }
        mn0 = fmaxf(mn0, __shfl_xor_sync(0xffffffff, mn0, 1));
        mn0 = fmaxf(mn0, __shfl_xor_sync(0xffffffff, mn0, 2));
        mn1 = fmaxf(mn1, __shfl_xor_sync(0xffffffff, mn1, 1));
        mn1 = fmaxf(mn1, __shfl_xor_sync(0xffffffff, mn1, 2));

        float corr0 = __expf(m0r - mn0);
        float corr1 = __expf(m1r - mn1);
        m0r = mn0; m1r = mn1;

        float ps0 = 0.f, ps1 = 0.f;
#pragma unroll
        for (int nt = 0; nt < 8; ++nt) {
            int c = nt * 8 + 2 * l;
            float p0 = __expf(s[nt][0] - mn0);
            float p1 = __expf(s[nt][1] - mn0);
            float p2 = __expf(s[nt][2] - mn1);
            float p3 = __expf(s[nt][3] - mn1);
            ps0 += p0 + p1; ps1 += p2 + p3;
            // store P (tf32-rounded bits) into Ps — warp-local rows only
            Ps[(wq + g) * PLD + c]     = __uint_as_float(f2tf(p0));
            Ps[(wq + g) * PLD + c + 1] = __uint_as_float(f2tf(p1));
            Ps[(wq + g + 8) * PLD + c]     = __uint_as_float(f2tf(p2));
            Ps[(wq + g + 8) * PLD + c + 1] = __uint_as_float(f2tf(p3));
        }
        ps0 += __shfl_xor_sync(0xffffffff, ps0, 1);
        ps0 += __shfl_xor_sync(0xffffffff, ps0, 2);
        ps1 += __shfl_xor_sync(0xffffffff, ps1, 1);
        ps1 += __shfl_xor_sync(0xffffffff, ps1, 2);
        l0r = l0r * corr0 + ps0;
        l1r = l1r * corr1 + ps1;

        // rescale O accumulators
#pragma unroll
        for (int nt = 0; nt < 4; ++nt) {
            o[nt][0] *= corr0; o[nt][1] *= corr0;
            o[nt][2] *= corr1; o[nt][3] *= corr1;
        }
        __syncwarp();

        // O += P @ V  (P rows are warp-local; V shared, loaded before sync)
#pragma unroll
        for (int ks = 0; ks < 8; ++ks) {
            const int k = ks * 8;
            unsigned a0 = __float_as_uint(Ps[(wq + g) * PLD + k + l]);
            unsigned a1 = __float_as_uint(Ps[(wq + g + 8) * PLD + k + l]);
            unsigned a2 = __float_as_uint(Ps[(wq + g) * PLD + k + l + 4]);
            unsigned a3 = __float_as_uint(Ps[(wq + g + 8) * PLD + k + l + 4]);
#pragma unroll
            for (int nt = 0; nt < 4; ++nt) {
                unsigned b0 = Vs[(k + l) * ALD + nt * 8 + g];
                unsigned b1 = Vs[(k + l + 4) * ALD + nt * 8 + g];
                mma_tf32(o[nt], a0, a1, a2, a3, b0, b1);
            }
        }
        __syncthreads();
    }

    const float inv0 = 1.0f / l0r;
    const float inv1 = 1.0f / l1r;
#pragma unroll
    for (int nt = 0; nt < 4; ++nt) {
        int r = q0 + wq + g;
        int c = hh * HDIM + nt * 8 + 2 * l;
        *(float2*)(AO + ((size_t)(b * NSEQ + r)) * DMODEL + c) =
            make_float2(o[nt][0] * inv0, o[nt][1] * inv0);
        *(float2*)(AO + ((size_t)(b * NSEQ + r + 8)) * DMODEL + c) =
            make_float2(o[nt][2] * inv1, o[nt][3] * inv1);
    }
}

// ----------------------------------------------------------------------------
// launch
// ----------------------------------------------------------------------------
extern "C" void kernel_launch(void* const* d_in, const int* in_sizes, int n_in,
                              void* d_out, int out_size)
{
    const float* h    = (const float*)d_in[0];
    const float* edge = (const float*)d_in[1];
    const int*   mask = (const int*)  d_in[2];
    const float* Wq   = (const float*)d_in[3];
    const float* Wk   = (const float*)d_in[4];
    const float* Wv   = (const float*)d_in[5];
    const float* We   = (const float*)d_in[6];
    const float* Wo   = (const float*)d_in[7];
    float* out = (float*)d_out;

    float *qs, *ks, *vs, *ao;
    cudaGetSymbolAddress((void**)&qs, g_q);
    cudaGetSymbolAddress((void**)&ks, g_k);
    cudaGetSymbolAddress((void**)&vs, g_v);
    cudaGetSymbolAddress((void**)&ao, g_ao);

    dim3 pgrid(DMODEL / 128, MROWS / 128);   // (2, 128)
    gemm_tf32<<<pgrid, 256>>>(h, Wq, qs);
    gemm_tf32<<<pgrid, 256>>>(h, Wk, ks);
    gemm_tf32<<<pgrid, 256>>>(h, Wv, vs);

    attn_tf32<<<dim3(NSEQ / 64, BATCH * NHEAD), 128>>>(qs, ks, vs, edge, mask, We, ao);

    gemm_tf32<<<pgrid, 256>>>(ao, Wo, out);
}